// round 8
// baseline (speedup 1.0000x reference)
#include <cuda_runtime.h>
#include <cuda_bf16.h>
#include <cstdint>

// ---------------------------------------------------------------------------
// AttentionDecoderRNN — GB300 (sm_103a): mma.sync bf16x3 GEMMs
//
// Precision: 3-product bf16 split folded into extended K:
//   A' = [Ahi | Ahi | Alo],  B' = [Bhi | Blo | Bhi]   (K' = 3K)
//   C  = A' @ B'^T (fp32 accum) = AhiBhi + AhiBlo + AloBhi  ~7e-6 rel err
//
// Round-7: CTA tile 128x256 / warp tile 64x64 (was 128x128 / 64x32).
// The old tile was smem-crossbar-bound through ldmatrix redundancy
// (0.19 B/MAC); the new tile cuts that 3.1x (0.061 B/MAC).
// ---------------------------------------------------------------------------

#define TB     64
#define TT     31
#define EMB    512
#define HID    1024
#define G4     4096
#define VOC    32000
#define MROWS  (TT * TB)   // 1984
#define MPAD   2048
#define KX     (3 * EMB)   // 1536
#define KL     (3 * HID)   // 3072

// fp32-path state
__device__ float g_ctx  [TB * HID];
__device__ float g_bias [G4];
__device__ int   g_rows [MROWS];
__device__ float g_gbase[TB * G4];
__device__ float g_gx   [MROWS * G4];
__device__ float g_h    [TB * HID];
__device__ float g_c    [TB * HID];
__device__ float g_part [4 * TB * G4];
__device__ float g_hs   [MROWS * HID];

// interleaved bf16x3 operands
__device__ __nv_bfloat16 g_WL3[VOC * KL];    // 196.6 MB
__device__ __nv_bfloat16 g_Wx3[G4 * KX];     // 12.6 MB
__device__ __nv_bfloat16 g_A3 [MPAD * KX];   // 6.3 MB
__device__ __nv_bfloat16 g_Hs3[MPAD * KL];   // 12.6 MB

// ======================= small helpers =====================================
__device__ __forceinline__ uint32_t smem_u32(const void* p) {
    uint32_t a;
    asm("{ .reg .u64 t; cvta.to.shared.u64 t, %1; cvt.u32.u64 %0, t; }"
        : "=r"(a) : "l"(p));
    return a;
}
__device__ __forceinline__ void ldsm4(uint32_t* r, uint32_t addr) {
    asm volatile("ldmatrix.sync.aligned.m8n8.x4.shared.b16 {%0,%1,%2,%3}, [%4];"
                 : "=r"(r[0]), "=r"(r[1]), "=r"(r[2]), "=r"(r[3]) : "r"(addr));
}
__device__ __forceinline__ void mma16816(float* c, const uint32_t* a,
                                         const uint32_t* b) {
    asm volatile(
        "mma.sync.aligned.m16n8k16.row.col.f32.bf16.bf16.f32 "
        "{%0,%1,%2,%3}, {%4,%5,%6,%7}, {%8,%9}, {%0,%1,%2,%3};"
        : "+f"(c[0]), "+f"(c[1]), "+f"(c[2]), "+f"(c[3])
        : "r"(a[0]), "r"(a[1]), "r"(a[2]), "r"(a[3]), "r"(b[0]), "r"(b[1]));
}
__device__ __forceinline__ void cpasync16(uint32_t s, const void* g) {
    asm volatile("cp.async.cg.shared.global [%0], [%1], 16;" :: "r"(s), "l"(g));
}
#define CP_COMMIT() asm volatile("cp.async.commit_group;" ::: "memory")
#define CP_WAIT1()  asm volatile("cp.async.wait_group 1;"  ::: "memory")

// ======================= split kernels =====================================
__device__ __forceinline__ void split1(float x, unsigned short& h, unsigned short& l) {
    __nv_bfloat16 hb = __float2bfloat16(x);
    __nv_bfloat16 lb = __float2bfloat16(x - __bfloat162float(hb));
    h = __bfloat16_as_ushort(hb);
    l = __bfloat16_as_ushort(lb);
}
__device__ __forceinline__ void split4(float4 v, ushort4& h, ushort4& l) {
    split1(v.x, h.x, l.x); split1(v.y, h.y, l.y);
    split1(v.z, h.z, l.z); split1(v.w, h.w, l.w);
}

// lin_W (32000 x 1024) -> WL3 rows [hi | lo | hi]
__global__ void split_lin(const float* __restrict__ src) {
    int i = blockIdx.x * blockDim.x + threadIdx.x;     // VOC*256
    if (i >= VOC * (HID / 4)) return;
    int r = i >> 8, c = (i & 255) * 4;
    float4 v = *(const float4*)(src + (size_t)r * HID + c);
    ushort4 h, l; split4(v, h, l);
    __nv_bfloat16* row = g_WL3 + (size_t)r * KL;
    *(ushort4*)(row + c)            = h;
    *(ushort4*)(row + HID + c)      = l;
    *(ushort4*)(row + 2 * HID + c)  = h;
}

// W_ih[:, :512] (pitch 1536) -> Wx3 rows [hi | lo | hi]
__global__ void split_wx(const float* __restrict__ src) {
    int i = blockIdx.x * blockDim.x + threadIdx.x;     // G4*128
    if (i >= G4 * (EMB / 4)) return;
    int r = i >> 7, c = (i & 127) * 4;
    float4 v = *(const float4*)(src + (size_t)r * (EMB + HID) + c);
    ushort4 h, l; split4(v, h, l);
    __nv_bfloat16* row = g_Wx3 + (size_t)r * KX;
    *(ushort4*)(row + c)            = h;
    *(ushort4*)(row + EMB + c)      = l;
    *(ushort4*)(row + 2 * EMB + c)  = h;
}

// Embed[rows] -> A3 rows [hi | hi | lo], zero-padded beyond MROWS
__global__ void split_emb(const float* __restrict__ embed) {
    int i = blockIdx.x * blockDim.x + threadIdx.x;     // MPAD*128
    if (i >= MPAD * (EMB / 4)) return;
    int r = i >> 7, c = (i & 127) * 4;
    float4 v = make_float4(0.f, 0.f, 0.f, 0.f);
    if (r < MROWS) v = *(const float4*)(embed + (size_t)g_rows[r] * EMB + c);
    ushort4 h, l; split4(v, h, l);
    __nv_bfloat16* row = g_A3 + (size_t)r * KX;
    *(ushort4*)(row + c)            = h;
    *(ushort4*)(row + EMB + c)      = h;
    *(ushort4*)(row + 2 * EMB + c)  = l;
}

// hs -> Hs3 rows [hi | hi | lo], zero-padded
__global__ void split_hs() {
    int i = blockIdx.x * blockDim.x + threadIdx.x;     // MPAD*256
    if (i >= MPAD * (HID / 4)) return;
    int r = i >> 8, c = (i & 255) * 4;
    float4 v = make_float4(0.f, 0.f, 0.f, 0.f);
    if (r < MROWS) v = *(const float4*)(g_hs + (size_t)r * HID + c);
    ushort4 h, l; split4(v, h, l);
    __nv_bfloat16* row = g_Hs3 + (size_t)r * KL;
    *(ushort4*)(row + c)            = h;
    *(ushort4*)(row + HID + c)      = h;
    *(ushort4*)(row + 2 * HID + c)  = l;
}

// ======================= bf16 mma.sync GEMM ================================
// C[M,N] = A[M,Kp] @ B[N,Kp]^T (+bias). Row-major A and B (B is "col" side).
// CTA 128x256, BK=32, 8 warps (2M x 4N, warp tile 64x64), 3-stage cp.async.
// smem rows: 32 bf16 (64B) padded to 80B pitch (conflict-free ldmatrix:
// 8 rows x 20-bank stride covers all 32 banks).
#define MM_BM    128
#define MM_BN    256
#define MM_BK    32
#define MM_PITCH 80
#define MM_ASZ   (MM_BM * MM_PITCH)     // 10240
#define MM_BSZ   (MM_BN * MM_PITCH)     // 20480
#define MM_STG   (MM_ASZ + MM_BSZ)      // 30720
#define MM_SMEM  (3 * MM_STG)           // 92160

__global__ __launch_bounds__(256, 1) void mma_gemm(
    const __nv_bfloat16* __restrict__ A,
    const __nv_bfloat16* __restrict__ B, int Kp,
    float* __restrict__ C, int ldc, int Mrows,
    const float* __restrict__ bias)
{
    extern __shared__ char sm[];
    const uint32_t sb = smem_u32(sm);
    const int tid = threadIdx.x;
    const int wid = tid >> 5, l = tid & 31;
    const int wm = wid & 1, wn = wid >> 1;      // 2M x 4N warps
    const int bm = blockIdx.x * MM_BM, bn = blockIdx.y * MM_BN;

    // cp.async mapping: thread t -> A row t>>1; B rows t>>1 and (t>>1)+128;
    // chunk pair (t&1)*2 (each chunk = 16B of the 64B row payload).
    const int row = tid >> 1, cb = (tid & 1) * 2;
    const char* gA  = (const char*)(A + (size_t)(bm + row) * Kp) + cb * 16;
    const char* gB0 = (const char*)(B + (size_t)(bn + row) * Kp) + cb * 16;
    const char* gB1 = (const char*)(B + (size_t)(bn + row + 128) * Kp) + cb * 16;
    const uint32_t sA  = (uint32_t)(row * MM_PITCH + cb * 16);
    const uint32_t sB0 = (uint32_t)(MM_ASZ + row * MM_PITCH + cb * 16);
    const uint32_t sB1 = sB0 + 128 * MM_PITCH;

    // ldmatrix per-lane base offsets
    const uint32_t aoff = (uint32_t)(
        (wm * 64 + (l & 7) + ((l >> 3) & 1) * 8) * MM_PITCH + (l >> 4) * 16);
    const uint32_t boff = (uint32_t)(
        MM_ASZ + (wn * 64 + (l & 7) + ((l >> 4) << 3)) * MM_PITCH
        + ((l >> 3) & 1) * 16);

    float acc[4][8][4];
#pragma unroll
    for (int a = 0; a < 4; ++a)
#pragma unroll
        for (int b = 0; b < 8; ++b)
#pragma unroll
            for (int q = 0; q < 4; ++q) acc[a][b][q] = 0.f;

    const int nc = Kp / MM_BK;

#define MM_ISSUE(s, ko) do {                                                 \
    uint32_t _st = sb + (s) * MM_STG;                                        \
    cpasync16(_st + sA,       gA  + (ko) * 2);                               \
    cpasync16(_st + sA  + 16, gA  + (ko) * 2 + 16);                          \
    cpasync16(_st + sB0,      gB0 + (ko) * 2);                               \
    cpasync16(_st + sB0 + 16, gB0 + (ko) * 2 + 16);                          \
    cpasync16(_st + sB1,      gB1 + (ko) * 2);                               \
    cpasync16(_st + sB1 + 16, gB1 + (ko) * 2 + 16);                          \
} while (0)

    MM_ISSUE(0, 0);  CP_COMMIT();
    MM_ISSUE(1, 32); CP_COMMIT();

    int cs = 0;            // consume stage = c % 3
    for (int c = 0; c < nc; ++c) {
        CP_WAIT1();
        __syncthreads();
        const uint32_t st = sb + cs * MM_STG;
#pragma unroll
        for (int kk = 0; kk < 2; ++kk) {
            uint32_t a4[4][4], b4[4][4];
#pragma unroll
            for (int mb = 0; mb < 4; ++mb)
                ldsm4(a4[mb], st + aoff + mb * (16 * MM_PITCH) + kk * 32);
#pragma unroll
            for (int nb = 0; nb < 4; ++nb)
                ldsm4(b4[nb], st + boff + nb * (16 * MM_PITCH) + kk * 32);
#pragma unroll
            for (int mb = 0; mb < 4; ++mb)
#pragma unroll
                for (int j = 0; j < 8; ++j)
                    mma16816(acc[mb][j], a4[mb], &b4[j >> 1][(j & 1) * 2]);
        }
        __syncthreads();
        const int nx = c + 2;                             // prefetch chunk
        const int ns = (cs + 2 >= 3) ? cs - 1 : cs + 2;   // (c+2) % 3
        if (nx < nc) MM_ISSUE(ns, nx * 32);
        CP_COMMIT();
        cs = (cs + 1 == 3) ? 0 : cs + 1;
    }
#undef MM_ISSUE

    // epilogue
    const int g4 = l >> 2, p2 = l & 3;
#pragma unroll
    for (int mb = 0; mb < 4; ++mb) {
        const int r0 = bm + wm * 64 + mb * 16 + g4;
#pragma unroll
        for (int j = 0; j < 8; ++j) {
            const int col = bn + wn * 64 + j * 8 + p2 * 2;
            float b0 = 0.f, b1 = 0.f;
            if (bias) { b0 = bias[col]; b1 = bias[col + 1]; }
            if (r0 < Mrows) {
                float2 v = make_float2(acc[mb][j][0] + b0, acc[mb][j][1] + b1);
                *(float2*)(C + (size_t)r0 * ldc + col) = v;
            }
            if (r0 + 8 < Mrows) {
                float2 v = make_float2(acc[mb][j][2] + b0, acc[mb][j][3] + b1);
                *(float2*)(C + (size_t)(r0 + 8) * ldc + col) = v;
            }
        }
    }
}

// ======================= fp32 path =========================================
__device__ __forceinline__ unsigned long long pk2(float x) {
    unsigned long long r;
    asm("mov.b64 %0, {%1, %2};" : "=l"(r) : "f"(x), "f"(x));
    return r;
}
__device__ __forceinline__ void unpk2(float& lo, float& hi, unsigned long long v) {
    asm("mov.b64 {%0, %1}, %2;" : "=f"(lo), "=f"(hi) : "l"(v));
}
#define FMA2(d, a, b) asm("fma.rn.f32x2 %0, %1, %2, %0;" : "+l"(d) : "l"(a), "l"(b))

__global__ void prep_kernel(const int* __restrict__ captions,
                            const float* __restrict__ bih,
                            const float* __restrict__ bhh) {
    int i = blockIdx.x * blockDim.x + threadIdx.x;
    if (i < G4) g_bias[i] = bih[i] + bhh[i];
    if (i < MROWS) {
        int t = i / TB, b = i % TB;
        g_rows[i] = captions[b * 32 + t];
    }
}

__global__ void ctx_kernel(const float* __restrict__ feat) {
    int idx = blockIdx.x * blockDim.x + threadIdx.x;
    int b = idx >> 10, d = idx & 1023;
    const float* p = feat + (size_t)b * 64 * HID + d;
    float s = 0.f;
#pragma unroll
    for (int ll = 0; ll < 64; ++ll) s += p[ll * HID];
    g_ctx[idx] = s;
}

__global__ __launch_bounds__(256) void sgemm_kernel(
    const float* __restrict__ A, int lda,
    const float* __restrict__ B, int ldb,
    float* __restrict__ C, int ldc,
    int Klen, int splitStride,
    const float* __restrict__ bias)
{
    __shared__ float As[8][68];
    __shared__ float Bs[8][132];

    const int tid = threadIdx.x;
    const int bm = blockIdx.x * 64;
    const int bn = blockIdx.y * 128;
    const int ks = blockIdx.z * Klen;
    C += (size_t)blockIdx.z * splitStride;

    const int tn8 = (tid & 15) * 8;
    const int tm4 = (tid >> 4) * 4;

    const float* Aptr = A + (size_t)(bm + (tid >> 1)) * lda + ks + (tid & 1) * 4;
    const float* Bptr = B + (size_t)(bn + (tid >> 1)) * ldb + ks + (tid & 1) * 4;

    float4 aReg = make_float4(0.f, 0.f, 0.f, 0.f), bReg;
    if (tid < 128) aReg = *(const float4*)Aptr;
    bReg = *(const float4*)Bptr;

    unsigned long long acc[4][4];
#pragma unroll
    for (int i = 0; i < 4; ++i)
#pragma unroll
        for (int j = 0; j < 4; ++j) acc[i][j] = 0ull;

    const int nChunks = Klen >> 3;
    for (int kc = 0; kc < nChunks; ++kc) {
        if (tid < 128) {
            int m = tid >> 1, k0 = (tid & 1) * 4;
            As[k0 + 0][m] = aReg.x; As[k0 + 1][m] = aReg.y;
            As[k0 + 2][m] = aReg.z; As[k0 + 3][m] = aReg.w;
        }
        {
            int n = tid >> 1, k0 = (tid & 1) * 4;
            Bs[k0 + 0][n] = bReg.x; Bs[k0 + 1][n] = bReg.y;
            Bs[k0 + 2][n] = bReg.z; Bs[k0 + 3][n] = bReg.w;
        }
        __syncthreads();
        if (kc + 1 < nChunks) {
            if (tid < 128) aReg = *(const float4*)(Aptr + (kc + 1) * 8);
            bReg = *(const float4*)(Bptr + (kc + 1) * 8);
        }
#pragma unroll
        for (int kk = 0; kk < 8; ++kk) {
            float4 av = *(const float4*)&As[kk][tm4];
            unsigned long long aa0 = pk2(av.x), aa1 = pk2(av.y),
                               aa2 = pk2(av.z), aa3 = pk2(av.w);
            const float* brow = &Bs[kk][tn8];
            unsigned long long b0 = *(const unsigned long long*)(brow + 0);
            unsigned long long b1 = *(const unsigned long long*)(brow + 2);
            unsigned long long b2 = *(const unsigned long long*)(brow + 4);
            unsigned long long b3 = *(const unsigned long long*)(brow + 6);
            FMA2(acc[0][0], aa0, b0); FMA2(acc[0][1], aa0, b1);
            FMA2(acc[0][2], aa0, b2); FMA2(acc[0][3], aa0, b3);
            FMA2(acc[1][0], aa1, b0); FMA2(acc[1][1], aa1, b1);
            FMA2(acc[1][2], aa1, b2); FMA2(acc[1][3], aa1, b3);
            FMA2(acc[2][0], aa2, b0); FMA2(acc[2][1], aa2, b1);
            FMA2(acc[2][2], aa2, b2); FMA2(acc[2][3], aa2, b3);
            FMA2(acc[3][0], aa3, b0); FMA2(acc[3][1], aa3, b1);
            FMA2(acc[3][2], aa3, b2); FMA2(acc[3][3], aa3, b3);
        }
        __syncthreads();
    }

    float bv[8];
    if (bias) {
        float4 t0 = *(const float4*)(bias + bn + tn8);
        float4 t1 = *(const float4*)(bias + bn + tn8 + 4);
        bv[0] = t0.x; bv[1] = t0.y; bv[2] = t0.z; bv[3] = t0.w;
        bv[4] = t1.x; bv[5] = t1.y; bv[6] = t1.z; bv[7] = t1.w;
    } else {
#pragma unroll
        for (int q = 0; q < 8; ++q) bv[q] = 0.f;
    }
#pragma unroll
    for (int im = 0; im < 4; ++im) {
        float o[8];
#pragma unroll
        for (int p = 0; p < 4; ++p) unpk2(o[2 * p], o[2 * p + 1], acc[im][p]);
#pragma unroll
        for (int q = 0; q < 8; ++q) o[q] += bv[q];
        float4* cp = reinterpret_cast<float4*>(
            C + (size_t)(bm + tm4 + im) * ldc + bn + tn8);
        cp[0] = make_float4(o[0], o[1], o[2], o[3]);
        cp[1] = make_float4(o[4], o[5], o[6], o[7]);
    }
}

__global__ void lstm_update(const float* __restrict__ gx_t, int t) {
    int idx = blockIdx.x * blockDim.x + threadIdx.x;
    int b = idx >> 10, j = idx & 1023;
    int base = b << 12;

    float gi = g_gbase[base + j]        + gx_t[base + j];
    float gf = g_gbase[base + 1024 + j] + gx_t[base + 1024 + j];
    float gg = g_gbase[base + 2048 + j] + gx_t[base + 2048 + j];
    float go = g_gbase[base + 3072 + j] + gx_t[base + 3072 + j];

    if (t > 0) {
#pragma unroll
        for (int s = 0; s < 4; ++s) {
            const float* pp = g_part + (size_t)s * TB * G4 + base;
            gi += pp[j];
            gf += pp[1024 + j];
            gg += pp[2048 + j];
            go += pp[3072 + j];
        }
    }

    float i_ = 1.f / (1.f + expf(-gi));
    float f_ = 1.f / (1.f + expf(-gf));
    float o_ = 1.f / (1.f + expf(-go));
    float g_ = tanhf(gg);

    float c_old = (t == 0) ? 0.f : g_c[idx];
    float cn = f_ * c_old + i_ * g_;
    float hn = o_ * tanhf(cn);

    g_c[idx] = cn;
    g_h[idx] = hn;
    g_hs[(size_t)t * (TB * HID) + idx] = hn;
}

// ---------------------------------------------------------------------------
extern "C" void kernel_launch(void* const* d_in, const int* in_sizes, int n_in,
                              void* d_out, int out_size) {
    const float* features = (const float*)d_in[0];
    const int*   captions = (const int*)  d_in[1];
    const float* embed    = (const float*)d_in[3];
    const float* W_ih     = (const float*)d_in[4];
    const float* W_hh     = (const float*)d_in[5];
    const float* b_ih     = (const float*)d_in[6];
    const float* b_hh     = (const float*)d_in[7];
    const float* lin_W    = (const float*)d_in[10];
    const float* lin_b    = (const float*)d_in[11];
    float* out = (float*)d_out;

    float *p_ctx, *p_gbase, *p_gx, *p_h, *p_part, *p_bias;
    cudaGetSymbolAddress((void**)&p_ctx,   g_ctx);
    cudaGetSymbolAddress((void**)&p_gbase, g_gbase);
    cudaGetSymbolAddress((void**)&p_gx,    g_gx);
    cudaGetSymbolAddress((void**)&p_h,     g_h);
    cudaGetSymbolAddress((void**)&p_part,  g_part);
    cudaGetSymbolAddress((void**)&p_bias,  g_bias);
    __nv_bfloat16 *p_WL3, *p_Wx3, *p_A3, *p_Hs3;
    cudaGetSymbolAddress((void**)&p_WL3, g_WL3);
    cudaGetSymbolAddress((void**)&p_Wx3, g_Wx3);
    cudaGetSymbolAddress((void**)&p_A3,  g_A3);
    cudaGetSymbolAddress((void**)&p_Hs3, g_Hs3);

    cudaFuncSetAttribute(mma_gemm, cudaFuncAttributeMaxDynamicSharedMemorySize,
                         MM_SMEM);

    prep_kernel<<<16, 256>>>(captions, b_ih, b_hh);
    ctx_kernel<<<(TB * HID) / 256, 256>>>(features);

    split_lin<<<(VOC * 256) / 256, 256>>>(lin_W);
    split_wx <<<(G4 * 128) / 256, 256>>>(W_ih);
    split_emb<<<(MPAD * 128) / 256, 256>>>(embed);

    // gbase = ctx @ W_ih[:,512:]^T + (b_ih + b_hh)   (fp32)
    sgemm_kernel<<<dim3(1, 32, 1), 256>>>(p_ctx, HID,
                                          W_ih + EMB, EMB + HID,
                                          p_gbase, G4, HID, 0, p_bias);

    // gx = A3 @ Wx3^T   (bf16x3)  M=2048 N=4096 K'=1536
    mma_gemm<<<dim3(MPAD / 128, G4 / 256), 256, MM_SMEM>>>(
        p_A3, p_Wx3, KX, p_gx, G4, MROWS, nullptr);

    for (int t = 0; t < TT; ++t) {
        if (t > 0) {
            sgemm_kernel<<<dim3(1, 32, 4), 256>>>(p_h, HID,
                                                  W_hh, HID,
                                                  p_part, G4, HID / 4,
                                                  TB * G4, nullptr);
        }
        lstm_update<<<(TB * HID) / 256, 256>>>(p_gx + (size_t)t * TB * G4, t);
    }

    split_hs<<<(MPAD * 256) / 256, 256>>>();

    // out = Hs3 @ WL3^T + lin_b   (bf16x3)  M=2048 N=32000 K'=3072
    mma_gemm<<<dim3(MPAD / 128, VOC / 256), 256, MM_SMEM>>>(
        p_Hs3, p_WL3, KL, out, VOC, MROWS, lin_b);
}

// round 9
// speedup vs baseline: 1.2156x; 1.2156x over previous
#include <cuda_runtime.h>
#include <cuda_bf16.h>
#include <cuda_fp16.h>
#include <cstdint>

// ---------------------------------------------------------------------------
// AttentionDecoderRNN — GB300 (sm_103a): mma.sync split-precision GEMMs
//
// Round-9: mma.sync HMMA rate is the bound (tile changes were neutral), so
// cut MAC count on the dominant GEMM:
//   - gx path (feeds LSTM): bf16 3-product, K'=3K  (error ~7e-6, unchanged)
//   - final logits GEMM:    fp16 2-product, K'=2K:
//       A' = [Ahi | Alo]  (A exact to ~2^-22),  B' = [Bhi | Bhi]
//       C  = A @ fp16(B)  -> norm rel err ~2e-4 (threshold 1e-3)
//     1/3 fewer MACs on 80% of the FLOPs; split_lin writes 131 MB vs 393 MB.
// ---------------------------------------------------------------------------

#define TB     64
#define TT     31
#define EMB    512
#define HID    1024
#define G4     4096
#define VOC    32000
#define MROWS  (TT * TB)   // 1984
#define MPAD   2048
#define KX     (3 * EMB)   // 1536  (bf16x3 gx path)
#define KL2    (2 * HID)   // 2048  (fp16x2 logits path)

// fp32-path state
__device__ float g_ctx  [TB * HID];
__device__ float g_bias [G4];
__device__ int   g_rows [MROWS];
__device__ float g_gbase[TB * G4];
__device__ float g_gx   [MROWS * G4];
__device__ float g_h    [TB * HID];
__device__ float g_c    [TB * HID];
__device__ float g_part [4 * TB * G4];
__device__ float g_hs   [MROWS * HID];

// split operands
__device__ __half        g_WL2[VOC * KL2];   // 131 MB  [hi|hi] fp16
__device__ __half        g_Hs2[MPAD * KL2];  // 8.4 MB  [hi|lo] fp16
__device__ __nv_bfloat16 g_Wx3[G4 * KX];     // 12.6 MB [hi|lo|hi] bf16
__device__ __nv_bfloat16 g_A3 [MPAD * KX];   // 6.3 MB  [hi|hi|lo] bf16

// ======================= small helpers =====================================
__device__ __forceinline__ uint32_t smem_u32(const void* p) {
    uint32_t a;
    asm("{ .reg .u64 t; cvta.to.shared.u64 t, %1; cvt.u32.u64 %0, t; }"
        : "=r"(a) : "l"(p));
    return a;
}
__device__ __forceinline__ void ldsm4(uint32_t* r, uint32_t addr) {
    asm volatile("ldmatrix.sync.aligned.m8n8.x4.shared.b16 {%0,%1,%2,%3}, [%4];"
                 : "=r"(r[0]), "=r"(r[1]), "=r"(r[2]), "=r"(r[3]) : "r"(addr));
}
template <bool F16>
__device__ __forceinline__ void mma16816(float* c, const uint32_t* a,
                                         const uint32_t* b) {
    if (F16) {
        asm volatile(
            "mma.sync.aligned.m16n8k16.row.col.f32.f16.f16.f32 "
            "{%0,%1,%2,%3}, {%4,%5,%6,%7}, {%8,%9}, {%0,%1,%2,%3};"
            : "+f"(c[0]), "+f"(c[1]), "+f"(c[2]), "+f"(c[3])
            : "r"(a[0]), "r"(a[1]), "r"(a[2]), "r"(a[3]), "r"(b[0]), "r"(b[1]));
    } else {
        asm volatile(
            "mma.sync.aligned.m16n8k16.row.col.f32.bf16.bf16.f32 "
            "{%0,%1,%2,%3}, {%4,%5,%6,%7}, {%8,%9}, {%0,%1,%2,%3};"
            : "+f"(c[0]), "+f"(c[1]), "+f"(c[2]), "+f"(c[3])
            : "r"(a[0]), "r"(a[1]), "r"(a[2]), "r"(a[3]), "r"(b[0]), "r"(b[1]));
    }
}
__device__ __forceinline__ void cpasync16(uint32_t s, const void* g) {
    asm volatile("cp.async.cg.shared.global [%0], [%1], 16;" :: "r"(s), "l"(g));
}
#define CP_COMMIT() asm volatile("cp.async.commit_group;" ::: "memory")
#define CP_WAIT1()  asm volatile("cp.async.wait_group 1;"  ::: "memory")

// ======================= split kernels =====================================
__device__ __forceinline__ void split1b(float x, unsigned short& h, unsigned short& l) {
    __nv_bfloat16 hb = __float2bfloat16(x);
    __nv_bfloat16 lb = __float2bfloat16(x - __bfloat162float(hb));
    h = __bfloat16_as_ushort(hb);
    l = __bfloat16_as_ushort(lb);
}
__device__ __forceinline__ void split4b(float4 v, ushort4& h, ushort4& l) {
    split1b(v.x, h.x, l.x); split1b(v.y, h.y, l.y);
    split1b(v.z, h.z, l.z); split1b(v.w, h.w, l.w);
}
__device__ __forceinline__ void split1h(float x, unsigned short& h, unsigned short& l) {
    __half hh = __float2half_rn(x);
    __half lh = __float2half_rn(x - __half2float(hh));
    h = __half_as_ushort(hh);
    l = __half_as_ushort(lh);
}

// lin_W (32000 x 1024) -> WL2 rows [hi | hi] fp16
__global__ void split_lin(const float* __restrict__ src) {
    int i = blockIdx.x * blockDim.x + threadIdx.x;     // VOC*256
    if (i >= VOC * (HID / 4)) return;
    int r = i >> 8, c = (i & 255) * 4;
    float4 v = *(const float4*)(src + (size_t)r * HID + c);
    ushort4 h;
    h.x = __half_as_ushort(__float2half_rn(v.x));
    h.y = __half_as_ushort(__float2half_rn(v.y));
    h.z = __half_as_ushort(__float2half_rn(v.z));
    h.w = __half_as_ushort(__float2half_rn(v.w));
    __half* row = g_WL2 + (size_t)r * KL2;
    *(ushort4*)(row + c)        = h;
    *(ushort4*)(row + HID + c)  = h;
}

// hs -> Hs2 rows [hi | lo] fp16, zero-padded
__global__ void split_hs() {
    int i = blockIdx.x * blockDim.x + threadIdx.x;     // MPAD*256
    if (i >= MPAD * (HID / 4)) return;
    int r = i >> 8, c = (i & 255) * 4;
    float4 v = make_float4(0.f, 0.f, 0.f, 0.f);
    if (r < MROWS) v = *(const float4*)(g_hs + (size_t)r * HID + c);
    ushort4 h, l;
    split1h(v.x, h.x, l.x); split1h(v.y, h.y, l.y);
    split1h(v.z, h.z, l.z); split1h(v.w, h.w, l.w);
    __half* row = g_Hs2 + (size_t)r * KL2;
    *(ushort4*)(row + c)        = h;
    *(ushort4*)(row + HID + c)  = l;
}

// W_ih[:, :512] (pitch 1536) -> Wx3 rows [hi | lo | hi] bf16
__global__ void split_wx(const float* __restrict__ src) {
    int i = blockIdx.x * blockDim.x + threadIdx.x;     // G4*128
    if (i >= G4 * (EMB / 4)) return;
    int r = i >> 7, c = (i & 127) * 4;
    float4 v = *(const float4*)(src + (size_t)r * (EMB + HID) + c);
    ushort4 h, l; split4b(v, h, l);
    __nv_bfloat16* row = g_Wx3 + (size_t)r * KX;
    *(ushort4*)(row + c)            = h;
    *(ushort4*)(row + EMB + c)      = l;
    *(ushort4*)(row + 2 * EMB + c)  = h;
}

// Embed[rows] -> A3 rows [hi | hi | lo] bf16, zero-padded beyond MROWS
__global__ void split_emb(const float* __restrict__ embed) {
    int i = blockIdx.x * blockDim.x + threadIdx.x;     // MPAD*128
    if (i >= MPAD * (EMB / 4)) return;
    int r = i >> 7, c = (i & 127) * 4;
    float4 v = make_float4(0.f, 0.f, 0.f, 0.f);
    if (r < MROWS) v = *(const float4*)(embed + (size_t)g_rows[r] * EMB + c);
    ushort4 h, l; split4b(v, h, l);
    __nv_bfloat16* row = g_A3 + (size_t)r * KX;
    *(ushort4*)(row + c)            = h;
    *(ushort4*)(row + EMB + c)      = h;
    *(ushort4*)(row + 2 * EMB + c)  = l;
}

// ======================= mma.sync GEMM (round-6 verified pipeline) =========
// C[M,N] = A[M,Kp] @ B[N,Kp]^T (+bias). Row-major A and B (B is "col" side).
// CTA 128x128, BK=32, 8 warps (2M x 4N, warp tile 64x32), 3-stage cp.async.
// smem rows: 32 elems (64B) padded to 80B pitch (conflict-free ldmatrix).
#define MM_BM   128
#define MM_BK   32
#define MM_PITCH 80
#define MM_ASZ  (MM_BM * MM_PITCH)     // 10240
#define MM_STG  (2 * MM_ASZ)           // 20480
#define MM_SMEM (3 * MM_STG)           // 61440

template <bool F16>
__global__ __launch_bounds__(256, 2) void mma_gemm(
    const void* __restrict__ Av,
    const void* __restrict__ Bv, int Kp,
    float* __restrict__ C, int ldc, int Mrows,
    const float* __restrict__ bias)
{
    const __half* A = (const __half*)Av;     // element size 2 either way
    const __half* B = (const __half*)Bv;
    extern __shared__ char sm[];
    const uint32_t sb = smem_u32(sm);
    const int tid = threadIdx.x;
    const int wid = tid >> 5, l = tid & 31;
    const int wm = wid & 1, wn = wid >> 1;
    const int bm = blockIdx.x * 128, bn = blockIdx.y * 128;

    // cp.async mapping: thread t handles rows (t>>2) and (t>>2)+64, chunk t&3
    const int row0 = tid >> 2, ch = tid & 3;
    const char* gA0 = (const char*)(A + (size_t)(bm + row0) * Kp) + ch * 16;
    const char* gA1 = (const char*)(A + (size_t)(bm + row0 + 64) * Kp) + ch * 16;
    const char* gB0 = (const char*)(B + (size_t)(bn + row0) * Kp) + ch * 16;
    const char* gB1 = (const char*)(B + (size_t)(bn + row0 + 64) * Kp) + ch * 16;
    const uint32_t sA0 = (uint32_t)(row0 * MM_PITCH + ch * 16);
    const uint32_t sA1 = sA0 + 64 * MM_PITCH;

    // ldmatrix per-lane offsets
    const int arow = wm * 64 + (l & 7) + ((l >> 3) & 1) * 8;
    const uint32_t aoff = (uint32_t)(arow * MM_PITCH + ((l >> 4) << 3) * 2);
    const int brow = wn * 32 + (l & 7) + ((l >> 4) << 3);
    const uint32_t boff = (uint32_t)(MM_ASZ + brow * MM_PITCH + ((l >> 3) & 1) * 16);

    float acc[4][4][4];
#pragma unroll
    for (int a = 0; a < 4; ++a)
#pragma unroll
        for (int b = 0; b < 4; ++b)
#pragma unroll
            for (int q = 0; q < 4; ++q) acc[a][b][q] = 0.f;

    const int nc = Kp / MM_BK;

#define MM_ISSUE(s, ko) do {                                                 \
    uint32_t _st = sb + (s) * MM_STG;                                        \
    cpasync16(_st + sA0, gA0 + (ko) * 2);                                    \
    cpasync16(_st + sA1, gA1 + (ko) * 2);                                    \
    cpasync16(_st + MM_ASZ + sA0, gB0 + (ko) * 2);                           \
    cpasync16(_st + MM_ASZ + sA1, gB1 + (ko) * 2);                           \
} while (0)

    MM_ISSUE(0, 0);  CP_COMMIT();
    MM_ISSUE(1, 32); CP_COMMIT();

    int cs = 0;            // consume stage = c % 3
    for (int c = 0; c < nc; ++c) {
        CP_WAIT1();
        __syncthreads();
        const uint32_t st = sb + cs * MM_STG;
#pragma unroll
        for (int kk = 0; kk < 2; ++kk) {
            uint32_t a4[4][4], b4[2][4];
#pragma unroll
            for (int mb = 0; mb < 4; ++mb)
                ldsm4(a4[mb], st + aoff + mb * (16 * MM_PITCH) + kk * 32);
#pragma unroll
            for (int nb = 0; nb < 2; ++nb)
                ldsm4(b4[nb], st + boff + nb * (16 * MM_PITCH) + kk * 32);
#pragma unroll
            for (int mb = 0; mb < 4; ++mb)
#pragma unroll
                for (int j = 0; j < 4; ++j)
                    mma16816<F16>(acc[mb][j], a4[mb], &b4[j >> 1][(j & 1) * 2]);
        }
        __syncthreads();
        const int nx = c + 2;                             // prefetch chunk
        const int ns = (cs + 2 >= 3) ? cs - 1 : cs + 2;   // (c+2) % 3
        if (nx < nc) MM_ISSUE(ns, nx * 32);
        CP_COMMIT();
        cs = (cs + 1 == 3) ? 0 : cs + 1;
    }
#undef MM_ISSUE

    // epilogue
    const int g4 = l >> 2, p2 = l & 3;
#pragma unroll
    for (int mb = 0; mb < 4; ++mb) {
        const int r0 = bm + wm * 64 + mb * 16 + g4;
#pragma unroll
        for (int j = 0; j < 4; ++j) {
            const int col = bn + wn * 32 + j * 8 + p2 * 2;
            float b0 = 0.f, b1 = 0.f;
            if (bias) { b0 = bias[col]; b1 = bias[col + 1]; }
            if (r0 < Mrows) {
                float2 v = make_float2(acc[mb][j][0] + b0, acc[mb][j][1] + b1);
                *(float2*)(C + (size_t)r0 * ldc + col) = v;
            }
            if (r0 + 8 < Mrows) {
                float2 v = make_float2(acc[mb][j][2] + b0, acc[mb][j][3] + b1);
                *(float2*)(C + (size_t)(r0 + 8) * ldc + col) = v;
            }
        }
    }
}

// ======================= fp32 path =========================================
__device__ __forceinline__ unsigned long long pk2(float x) {
    unsigned long long r;
    asm("mov.b64 %0, {%1, %2};" : "=l"(r) : "f"(x), "f"(x));
    return r;
}
__device__ __forceinline__ void unpk2(float& lo, float& hi, unsigned long long v) {
    asm("mov.b64 {%0, %1}, %2;" : "=f"(lo), "=f"(hi) : "l"(v));
}
#define FMA2(d, a, b) asm("fma.rn.f32x2 %0, %1, %2, %0;" : "+l"(d) : "l"(a), "l"(b))

__global__ void prep_kernel(const int* __restrict__ captions,
                            const float* __restrict__ bih,
                            const float* __restrict__ bhh) {
    int i = blockIdx.x * blockDim.x + threadIdx.x;
    if (i < G4) g_bias[i] = bih[i] + bhh[i];
    if (i < MROWS) {
        int t = i / TB, b = i % TB;
        g_rows[i] = captions[b * 32 + t];
    }
}

__global__ void ctx_kernel(const float* __restrict__ feat) {
    int idx = blockIdx.x * blockDim.x + threadIdx.x;
    int b = idx >> 10, d = idx & 1023;
    const float* p = feat + (size_t)b * 64 * HID + d;
    float s = 0.f;
#pragma unroll
    for (int ll = 0; ll < 64; ++ll) s += p[ll * HID];
    g_ctx[idx] = s;
}

__global__ __launch_bounds__(256) void sgemm_kernel(
    const float* __restrict__ A, int lda,
    const float* __restrict__ B, int ldb,
    float* __restrict__ C, int ldc,
    int Klen, int splitStride,
    const float* __restrict__ bias)
{
    __shared__ float As[8][68];
    __shared__ float Bs[8][132];

    const int tid = threadIdx.x;
    const int bm = blockIdx.x * 64;
    const int bn = blockIdx.y * 128;
    const int ks = blockIdx.z * Klen;
    C += (size_t)blockIdx.z * splitStride;

    const int tn8 = (tid & 15) * 8;
    const int tm4 = (tid >> 4) * 4;

    const float* Aptr = A + (size_t)(bm + (tid >> 1)) * lda + ks + (tid & 1) * 4;
    const float* Bptr = B + (size_t)(bn + (tid >> 1)) * ldb + ks + (tid & 1) * 4;

    float4 aReg = make_float4(0.f, 0.f, 0.f, 0.f), bReg;
    if (tid < 128) aReg = *(const float4*)Aptr;
    bReg = *(const float4*)Bptr;

    unsigned long long acc[4][4];
#pragma unroll
    for (int i = 0; i < 4; ++i)
#pragma unroll
        for (int j = 0; j < 4; ++j) acc[i][j] = 0ull;

    const int nChunks = Klen >> 3;
    for (int kc = 0; kc < nChunks; ++kc) {
        if (tid < 128) {
            int m = tid >> 1, k0 = (tid & 1) * 4;
            As[k0 + 0][m] = aReg.x; As[k0 + 1][m] = aReg.y;
            As[k0 + 2][m] = aReg.z; As[k0 + 3][m] = aReg.w;
        }
        {
            int n = tid >> 1, k0 = (tid & 1) * 4;
            Bs[k0 + 0][n] = bReg.x; Bs[k0 + 1][n] = bReg.y;
            Bs[k0 + 2][n] = bReg.z; Bs[k0 + 3][n] = bReg.w;
        }
        __syncthreads();
        if (kc + 1 < nChunks) {
            if (tid < 128) aReg = *(const float4*)(Aptr + (kc + 1) * 8);
            bReg = *(const float4*)(Bptr + (kc + 1) * 8);
        }
#pragma unroll
        for (int kk = 0; kk < 8; ++kk) {
            float4 av = *(const float4*)&As[kk][tm4];
            unsigned long long aa0 = pk2(av.x), aa1 = pk2(av.y),
                               aa2 = pk2(av.z), aa3 = pk2(av.w);
            const float* brow = &Bs[kk][tn8];
            unsigned long long b0 = *(const unsigned long long*)(brow + 0);
            unsigned long long b1 = *(const unsigned long long*)(brow + 2);
            unsigned long long b2 = *(const unsigned long long*)(brow + 4);
            unsigned long long b3 = *(const unsigned long long*)(brow + 6);
            FMA2(acc[0][0], aa0, b0); FMA2(acc[0][1], aa0, b1);
            FMA2(acc[0][2], aa0, b2); FMA2(acc[0][3], aa0, b3);
            FMA2(acc[1][0], aa1, b0); FMA2(acc[1][1], aa1, b1);
            FMA2(acc[1][2], aa1, b2); FMA2(acc[1][3], aa1, b3);
            FMA2(acc[2][0], aa2, b0); FMA2(acc[2][1], aa2, b1);
            FMA2(acc[2][2], aa2, b2); FMA2(acc[2][3], aa2, b3);
            FMA2(acc[3][0], aa3, b0); FMA2(acc[3][1], aa3, b1);
            FMA2(acc[3][2], aa3, b2); FMA2(acc[3][3], aa3, b3);
        }
        __syncthreads();
    }

    float bv[8];
    if (bias) {
        float4 t0 = *(const float4*)(bias + bn + tn8);
        float4 t1 = *(const float4*)(bias + bn + tn8 + 4);
        bv[0] = t0.x; bv[1] = t0.y; bv[2] = t0.z; bv[3] = t0.w;
        bv[4] = t1.x; bv[5] = t1.y; bv[6] = t1.z; bv[7] = t1.w;
    } else {
#pragma unroll
        for (int q = 0; q < 8; ++q) bv[q] = 0.f;
    }
#pragma unroll
    for (int im = 0; im < 4; ++im) {
        float o[8];
#pragma unroll
        for (int p = 0; p < 4; ++p) unpk2(o[2 * p], o[2 * p + 1], acc[im][p]);
#pragma unroll
        for (int q = 0; q < 8; ++q) o[q] += bv[q];
        float4* cp = reinterpret_cast<float4*>(
            C + (size_t)(bm + tm4 + im) * ldc + bn + tn8);
        cp[0] = make_float4(o[0], o[1], o[2], o[3]);
        cp[1] = make_float4(o[4], o[5], o[6], o[7]);
    }
}

__global__ void lstm_update(const float* __restrict__ gx_t, int t) {
    int idx = blockIdx.x * blockDim.x + threadIdx.x;
    int b = idx >> 10, j = idx & 1023;
    int base = b << 12;

    float gi = g_gbase[base + j]        + gx_t[base + j];
    float gf = g_gbase[base + 1024 + j] + gx_t[base + 1024 + j];
    float gg = g_gbase[base + 2048 + j] + gx_t[base + 2048 + j];
    float go = g_gbase[base + 3072 + j] + gx_t[base + 3072 + j];

    if (t > 0) {
#pragma unroll
        for (int s = 0; s < 4; ++s) {
            const float* pp = g_part + (size_t)s * TB * G4 + base;
            gi += pp[j];
            gf += pp[1024 + j];
            gg += pp[2048 + j];
            go += pp[3072 + j];
        }
    }

    float i_ = 1.f / (1.f + expf(-gi));
    float f_ = 1.f / (1.f + expf(-gf));
    float o_ = 1.f / (1.f + expf(-go));
    float g_ = tanhf(gg);

    float c_old = (t == 0) ? 0.f : g_c[idx];
    float cn = f_ * c_old + i_ * g_;
    float hn = o_ * tanhf(cn);

    g_c[idx] = cn;
    g_h[idx] = hn;
    g_hs[(size_t)t * (TB * HID) + idx] = hn;
}

// ---------------------------------------------------------------------------
extern "C" void kernel_launch(void* const* d_in, const int* in_sizes, int n_in,
                              void* d_out, int out_size) {
    const float* features = (const float*)d_in[0];
    const int*   captions = (const int*)  d_in[1];
    const float* embed    = (const float*)d_in[3];
    const float* W_ih     = (const float*)d_in[4];
    const float* W_hh     = (const float*)d_in[5];
    const float* b_ih     = (const float*)d_in[6];
    const float* b_hh     = (const float*)d_in[7];
    const float* lin_W    = (const float*)d_in[10];
    const float* lin_b    = (const float*)d_in[11];
    float* out = (float*)d_out;

    float *p_ctx, *p_gbase, *p_gx, *p_h, *p_part, *p_bias;
    cudaGetSymbolAddress((void**)&p_ctx,   g_ctx);
    cudaGetSymbolAddress((void**)&p_gbase, g_gbase);
    cudaGetSymbolAddress((void**)&p_gx,    g_gx);
    cudaGetSymbolAddress((void**)&p_h,     g_h);
    cudaGetSymbolAddress((void**)&p_part,  g_part);
    cudaGetSymbolAddress((void**)&p_bias,  g_bias);
    void *p_WL2, *p_Hs2, *p_Wx3, *p_A3;
    cudaGetSymbolAddress(&p_WL2, g_WL2);
    cudaGetSymbolAddress(&p_Hs2, g_Hs2);
    cudaGetSymbolAddress(&p_Wx3, g_Wx3);
    cudaGetSymbolAddress(&p_A3,  g_A3);

    cudaFuncSetAttribute(mma_gemm<false>,
                         cudaFuncAttributeMaxDynamicSharedMemorySize, MM_SMEM);
    cudaFuncSetAttribute(mma_gemm<true>,
                         cudaFuncAttributeMaxDynamicSharedMemorySize, MM_SMEM);

    prep_kernel<<<16, 256>>>(captions, b_ih, b_hh);
    ctx_kernel<<<(TB * HID) / 256, 256>>>(features);

    split_lin<<<(VOC * 256) / 256, 256>>>(lin_W);
    split_wx <<<(G4 * 128) / 256, 256>>>(W_ih);
    split_emb<<<(MPAD * 128) / 256, 256>>>(embed);

    // gbase = ctx @ W_ih[:,512:]^T + (b_ih + b_hh)   (fp32)
    sgemm_kernel<<<dim3(1, 32, 1), 256>>>(p_ctx, HID,
                                          W_ih + EMB, EMB + HID,
                                          p_gbase, G4, HID, 0, p_bias);

    // gx = A3 @ Wx3^T   (bf16x3)  M=2048 N=4096 K'=1536
    mma_gemm<false><<<dim3(MPAD / 128, G4 / 128), 256, MM_SMEM>>>(
        p_A3, p_Wx3, KX, p_gx, G4, MROWS, nullptr);

    for (int t = 0; t < TT; ++t) {
        if (t > 0) {
            sgemm_kernel<<<dim3(1, 32, 4), 256>>>(p_h, HID,
                                                  W_hh, HID,
                                                  p_part, G4, HID / 4,
                                                  TB * G4, nullptr);
        }
        lstm_update<<<(TB * HID) / 256, 256>>>(p_gx + (size_t)t * TB * G4, t);
    }

    split_hs<<<(MPAD * 256) / 256, 256>>>();

    // out = Hs2 @ WL2^T + lin_b   (fp16x2)  M=2048 N=32000 K'=2048
    mma_gemm<true><<<dim3(MPAD / 128, VOC / 128), 256, MM_SMEM>>>(
        p_Hs2, p_WL2, KL2, out, VOC, MROWS, lin_b);
}

// round 11
// speedup vs baseline: 1.5410x; 1.2677x over previous
#include <cuda_runtime.h>
#include <cuda_bf16.h>
#include <cuda_fp16.h>
#include <cstdint>

// ---------------------------------------------------------------------------
// AttentionDecoderRNN — GB300 (sm_103a): mma.sync split-precision GEMMs
//
// Round-10:
//   - logits GEMM: plain fp16 x fp16, K=1024 (no split). Error model
//     validated in R9: one quantized side = 2.07e-4; two sides ~2.9e-4
//     (threshold 1e-3). Half the MACs of R9's K'=2048.
//   - recurrence h@W_hh: split-K 8 (256 CTAs; was 128, <1 wave).
//   - gx path (feeds LSTM) stays bf16 3-product (error 7e-6, no
//     compounding through the 31-step recurrence).
// ---------------------------------------------------------------------------

#define TB     64
#define TT     31
#define EMB    512
#define HID    1024
#define G4     4096
#define VOC    32000
#define MROWS  (TT * TB)   // 1984
#define MPAD   2048
#define KX     (3 * EMB)   // 1536  (bf16x3 gx path)
#define RSPLIT 8           // recurrence split-K

// fp32-path state
__device__ float g_ctx  [TB * HID];
__device__ float g_bias [G4];
__device__ int   g_rows [MROWS];
__device__ float g_gbase[TB * G4];
__device__ float g_gx   [MROWS * G4];
__device__ float g_h    [TB * HID];
__device__ float g_c    [TB * HID];
__device__ float g_part [RSPLIT * TB * G4];
__device__ float g_hs   [MROWS * HID];

// split operands
__device__ __half        g_WL1[VOC * HID];   // 65.5 MB fp16
__device__ __half        g_Hs1[MPAD * HID];  // 4.2 MB  fp16
__device__ __nv_bfloat16 g_Wx3[G4 * KX];     // 12.6 MB [hi|lo|hi] bf16
__device__ __nv_bfloat16 g_A3 [MPAD * KX];   // 6.3 MB  [hi|hi|lo] bf16

// ======================= small helpers =====================================
__device__ __forceinline__ uint32_t smem_u32(const void* p) {
    uint32_t a;
    asm("{ .reg .u64 t; cvta.to.shared.u64 t, %1; cvt.u32.u64 %0, t; }"
        : "=r"(a) : "l"(p));
    return a;
}
__device__ __forceinline__ void ldsm4(uint32_t* r, uint32_t addr) {
    asm volatile("ldmatrix.sync.aligned.m8n8.x4.shared.b16 {%0,%1,%2,%3}, [%4];"
                 : "=r"(r[0]), "=r"(r[1]), "=r"(r[2]), "=r"(r[3]) : "r"(addr));
}
template <bool F16>
__device__ __forceinline__ void mma16816(float* c, const uint32_t* a,
                                         const uint32_t* b) {
    if (F16) {
        asm volatile(
            "mma.sync.aligned.m16n8k16.row.col.f32.f16.f16.f32 "
            "{%0,%1,%2,%3}, {%4,%5,%6,%7}, {%8,%9}, {%0,%1,%2,%3};"
            : "+f"(c[0]), "+f"(c[1]), "+f"(c[2]), "+f"(c[3])
            : "r"(a[0]), "r"(a[1]), "r"(a[2]), "r"(a[3]), "r"(b[0]), "r"(b[1]));
    } else {
        asm volatile(
            "mma.sync.aligned.m16n8k16.row.col.f32.bf16.bf16.f32 "
            "{%0,%1,%2,%3}, {%4,%5,%6,%7}, {%8,%9}, {%0,%1,%2,%3};"
            : "+f"(c[0]), "+f"(c[1]), "+f"(c[2]), "+f"(c[3])
            : "r"(a[0]), "r"(a[1]), "r"(a[2]), "r"(a[3]), "r"(b[0]), "r"(b[1]));
    }
}
__device__ __forceinline__ void cpasync16(uint32_t s, const void* g) {
    asm volatile("cp.async.cg.shared.global [%0], [%1], 16;" :: "r"(s), "l"(g));
}
#define CP_COMMIT() asm volatile("cp.async.commit_group;" ::: "memory")
#define CP_WAIT1()  asm volatile("cp.async.wait_group 1;"  ::: "memory")

// ======================= split kernels =====================================
__device__ __forceinline__ void split1b(float x, unsigned short& h, unsigned short& l) {
    __nv_bfloat16 hb = __float2bfloat16(x);
    __nv_bfloat16 lb = __float2bfloat16(x - __bfloat162float(hb));
    h = __bfloat16_as_ushort(hb);
    l = __bfloat16_as_ushort(lb);
}
__device__ __forceinline__ void split4b(float4 v, ushort4& h, ushort4& l) {
    split1b(v.x, h.x, l.x); split1b(v.y, h.y, l.y);
    split1b(v.z, h.z, l.z); split1b(v.w, h.w, l.w);
}
__device__ __forceinline__ ushort4 cvt4h(float4 v) {
    ushort4 h;
    h.x = __half_as_ushort(__float2half_rn(v.x));
    h.y = __half_as_ushort(__float2half_rn(v.y));
    h.z = __half_as_ushort(__float2half_rn(v.z));
    h.w = __half_as_ushort(__float2half_rn(v.w));
    return h;
}

// lin_W (32000 x 1024) -> WL1 fp16
__global__ void split_lin(const float* __restrict__ src) {
    int i = blockIdx.x * blockDim.x + threadIdx.x;     // VOC*256
    if (i >= VOC * (HID / 4)) return;
    ((ushort4*)g_WL1)[i] = cvt4h(((const float4*)src)[i]);
}

// hs -> Hs1 fp16, zero-padded
__global__ void split_hs() {
    int i = blockIdx.x * blockDim.x + threadIdx.x;     // MPAD*256
    if (i >= MPAD * (HID / 4)) return;
    int r = i >> 8;
    float4 v = make_float4(0.f, 0.f, 0.f, 0.f);
    if (r < MROWS) v = ((const float4*)g_hs)[i];
    ((ushort4*)g_Hs1)[i] = cvt4h(v);
}

// W_ih[:, :512] (pitch 1536) -> Wx3 rows [hi | lo | hi] bf16
__global__ void split_wx(const float* __restrict__ src) {
    int i = blockIdx.x * blockDim.x + threadIdx.x;     // G4*128
    if (i >= G4 * (EMB / 4)) return;
    int r = i >> 7, c = (i & 127) * 4;
    float4 v = *(const float4*)(src + (size_t)r * (EMB + HID) + c);
    ushort4 h, l; split4b(v, h, l);
    __nv_bfloat16* row = g_Wx3 + (size_t)r * KX;
    *(ushort4*)(row + c)            = h;
    *(ushort4*)(row + EMB + c)      = l;
    *(ushort4*)(row + 2 * EMB + c)  = h;
}

// Embed[rows] -> A3 rows [hi | hi | lo] bf16, zero-padded beyond MROWS
__global__ void split_emb(const float* __restrict__ embed) {
    int i = blockIdx.x * blockDim.x + threadIdx.x;     // MPAD*128
    if (i >= MPAD * (EMB / 4)) return;
    int r = i >> 7, c = (i & 127) * 4;
    float4 v = make_float4(0.f, 0.f, 0.f, 0.f);
    if (r < MROWS) v = *(const float4*)(embed + (size_t)g_rows[r] * EMB + c);
    ushort4 h, l; split4b(v, h, l);
    __nv_bfloat16* row = g_A3 + (size_t)r * KX;
    *(ushort4*)(row + c)            = h;
    *(ushort4*)(row + EMB + c)      = h;
    *(ushort4*)(row + 2 * EMB + c)  = l;
}

// ======================= mma.sync GEMM (round-6 verified pipeline) =========
// C[M,N] = A[M,Kp] @ B[N,Kp]^T (+bias). Row-major A and B (B is "col" side).
// CTA 128x128, BK=32, 8 warps (2M x 4N, warp tile 64x32), 3-stage cp.async.
// smem rows: 32 elems (64B) padded to 80B pitch (conflict-free ldmatrix).
#define MM_BM   128
#define MM_BK   32
#define MM_PITCH 80
#define MM_ASZ  (MM_BM * MM_PITCH)     // 10240
#define MM_STG  (2 * MM_ASZ)           // 20480
#define MM_SMEM (3 * MM_STG)           // 61440

template <bool F16>
__global__ __launch_bounds__(256, 2) void mma_gemm(
    const void* __restrict__ Av,
    const void* __restrict__ Bv, int Kp,
    float* __restrict__ C, int ldc, int Mrows,
    const float* __restrict__ bias)
{
    const __half* A = (const __half*)Av;     // element size 2 either way
    const __half* B = (const __half*)Bv;
    extern __shared__ char sm[];
    const uint32_t sb = smem_u32(sm);
    const int tid = threadIdx.x;
    const int wid = tid >> 5, l = tid & 31;
    const int wm = wid & 1, wn = wid >> 1;
    const int bm = blockIdx.x * 128, bn = blockIdx.y * 128;

    // cp.async mapping: thread t handles rows (t>>2) and (t>>2)+64, chunk t&3
    const int row0 = tid >> 2, ch = tid & 3;
    const char* gA0 = (const char*)(A + (size_t)(bm + row0) * Kp) + ch * 16;
    const char* gA1 = (const char*)(A + (size_t)(bm + row0 + 64) * Kp) + ch * 16;
    const char* gB0 = (const char*)(B + (size_t)(bn + row0) * Kp) + ch * 16;
    const char* gB1 = (const char*)(B + (size_t)(bn + row0 + 64) * Kp) + ch * 16;
    const uint32_t sA0 = (uint32_t)(row0 * MM_PITCH + ch * 16);
    const uint32_t sA1 = sA0 + 64 * MM_PITCH;

    // ldmatrix per-lane offsets
    const int arow = wm * 64 + (l & 7) + ((l >> 3) & 1) * 8;
    const uint32_t aoff = (uint32_t)(arow * MM_PITCH + ((l >> 4) << 3) * 2);
    const int brow = wn * 32 + (l & 7) + ((l >> 4) << 3);
    const uint32_t boff = (uint32_t)(MM_ASZ + brow * MM_PITCH + ((l >> 3) & 1) * 16);

    float acc[4][4][4];
#pragma unroll
    for (int a = 0; a < 4; ++a)
#pragma unroll
        for (int b = 0; b < 4; ++b)
#pragma unroll
            for (int q = 0; q < 4; ++q) acc[a][b][q] = 0.f;

    const int nc = Kp / MM_BK;

#define MM_ISSUE(s, ko) do {                                                 \
    uint32_t _st = sb + (s) * MM_STG;                                        \
    cpasync16(_st + sA0, gA0 + (ko) * 2);                                    \
    cpasync16(_st + sA1, gA1 + (ko) * 2);                                    \
    cpasync16(_st + MM_ASZ + sA0, gB0 + (ko) * 2);                           \
    cpasync16(_st + MM_ASZ + sA1, gB1 + (ko) * 2);                           \
} while (0)

    MM_ISSUE(0, 0);  CP_COMMIT();
    MM_ISSUE(1, 32); CP_COMMIT();

    int cs = 0;            // consume stage = c % 3
    for (int c = 0; c < nc; ++c) {
        CP_WAIT1();
        __syncthreads();
        const uint32_t st = sb + cs * MM_STG;
#pragma unroll
        for (int kk = 0; kk < 2; ++kk) {
            uint32_t a4[4][4], b4[2][4];
#pragma unroll
            for (int mb = 0; mb < 4; ++mb)
                ldsm4(a4[mb], st + aoff + mb * (16 * MM_PITCH) + kk * 32);
#pragma unroll
            for (int nb = 0; nb < 2; ++nb)
                ldsm4(b4[nb], st + boff + nb * (16 * MM_PITCH) + kk * 32);
#pragma unroll
            for (int mb = 0; mb < 4; ++mb)
#pragma unroll
                for (int j = 0; j < 4; ++j)
                    mma16816<F16>(acc[mb][j], a4[mb], &b4[j >> 1][(j & 1) * 2]);
        }
        __syncthreads();
        const int nx = c + 2;                             // prefetch chunk
        const int ns = (cs + 2 >= 3) ? cs - 1 : cs + 2;   // (c+2) % 3
        if (nx < nc) MM_ISSUE(ns, nx * 32);
        CP_COMMIT();
        cs = (cs + 1 == 3) ? 0 : cs + 1;
    }
#undef MM_ISSUE

    // epilogue
    const int g4 = l >> 2, p2 = l & 3;
#pragma unroll
    for (int mb = 0; mb < 4; ++mb) {
        const int r0 = bm + wm * 64 + mb * 16 + g4;
#pragma unroll
        for (int j = 0; j < 4; ++j) {
            const int col = bn + wn * 32 + j * 8 + p2 * 2;
            float b0 = 0.f, b1 = 0.f;
            if (bias) { b0 = bias[col]; b1 = bias[col + 1]; }
            if (r0 < Mrows) {
                float2 v = make_float2(acc[mb][j][0] + b0, acc[mb][j][1] + b1);
                *(float2*)(C + (size_t)r0 * ldc + col) = v;
            }
            if (r0 + 8 < Mrows) {
                float2 v = make_float2(acc[mb][j][2] + b0, acc[mb][j][3] + b1);
                *(float2*)(C + (size_t)(r0 + 8) * ldc + col) = v;
            }
        }
    }
}

// ======================= fp32 path =========================================
__device__ __forceinline__ unsigned long long pk2(float x) {
    unsigned long long r;
    asm("mov.b64 %0, {%1, %2};" : "=l"(r) : "f"(x), "f"(x));
    return r;
}
__device__ __forceinline__ void unpk2(float& lo, float& hi, unsigned long long v) {
    asm("mov.b64 {%0, %1}, %2;" : "=f"(lo), "=f"(hi) : "l"(v));
}
#define FMA2(d, a, b) asm("fma.rn.f32x2 %0, %1, %2, %0;" : "+l"(d) : "l"(a), "l"(b))

__global__ void prep_kernel(const int* __restrict__ captions,
                            const float* __restrict__ bih,
                            const float* __restrict__ bhh) {
    int i = blockIdx.x * blockDim.x + threadIdx.x;
    if (i < G4) g_bias[i] = bih[i] + bhh[i];
    if (i < MROWS) {
        int t = i / TB, b = i % TB;
        g_rows[i] = captions[b * 32 + t];
    }
}

__global__ void ctx_kernel(const float* __restrict__ feat) {
    int idx = blockIdx.x * blockDim.x + threadIdx.x;
    int b = idx >> 10, d = idx & 1023;
    const float* p = feat + (size_t)b * 64 * HID + d;
    float s = 0.f;
#pragma unroll
    for (int ll = 0; ll < 64; ++ll) s += p[ll * HID];
    g_ctx[idx] = s;
}

__global__ __launch_bounds__(256) void sgemm_kernel(
    const float* __restrict__ A, int lda,
    const float* __restrict__ B, int ldb,
    float* __restrict__ C, int ldc,
    int Klen, int splitStride,
    const float* __restrict__ bias)
{
    __shared__ float As[8][68];
    __shared__ float Bs[8][132];

    const int tid = threadIdx.x;
    const int bm = blockIdx.x * 64;
    const int bn = blockIdx.y * 128;
    const int ks = blockIdx.z * Klen;
    C += (size_t)blockIdx.z * splitStride;

    const int tn8 = (tid & 15) * 8;
    const int tm4 = (tid >> 4) * 4;

    const float* Aptr = A + (size_t)(bm + (tid >> 1)) * lda + ks + (tid & 1) * 4;
    const float* Bptr = B + (size_t)(bn + (tid >> 1)) * ldb + ks + (tid & 1) * 4;

    float4 aReg = make_float4(0.f, 0.f, 0.f, 0.f), bReg;
    if (tid < 128) aReg = *(const float4*)Aptr;
    bReg = *(const float4*)Bptr;

    unsigned long long acc[4][4];
#pragma unroll
    for (int i = 0; i < 4; ++i)
#pragma unroll
        for (int j = 0; j < 4; ++j) acc[i][j] = 0ull;

    const int nChunks = Klen >> 3;
    for (int kc = 0; kc < nChunks; ++kc) {
        if (tid < 128) {
            int m = tid >> 1, k0 = (tid & 1) * 4;
            As[k0 + 0][m] = aReg.x; As[k0 + 1][m] = aReg.y;
            As[k0 + 2][m] = aReg.z; As[k0 + 3][m] = aReg.w;
        }
        {
            int n = tid >> 1, k0 = (tid & 1) * 4;
            Bs[k0 + 0][n] = bReg.x; Bs[k0 + 1][n] = bReg.y;
            Bs[k0 + 2][n] = bReg.z; Bs[k0 + 3][n] = bReg.w;
        }
        __syncthreads();
        if (kc + 1 < nChunks) {
            if (tid < 128) aReg = *(const float4*)(Aptr + (kc + 1) * 8);
            bReg = *(const float4*)(Bptr + (kc + 1) * 8);
        }
#pragma unroll
        for (int kk = 0; kk < 8; ++kk) {
            float4 av = *(const float4*)&As[kk][tm4];
            unsigned long long aa0 = pk2(av.x), aa1 = pk2(av.y),
                               aa2 = pk2(av.z), aa3 = pk2(av.w);
            const float* brow = &Bs[kk][tn8];
            unsigned long long b0 = *(const unsigned long long*)(brow + 0);
            unsigned long long b1 = *(const unsigned long long*)(brow + 2);
            unsigned long long b2 = *(const unsigned long long*)(brow + 4);
            unsigned long long b3 = *(const unsigned long long*)(brow + 6);
            FMA2(acc[0][0], aa0, b0); FMA2(acc[0][1], aa0, b1);
            FMA2(acc[0][2], aa0, b2); FMA2(acc[0][3], aa0, b3);
            FMA2(acc[1][0], aa1, b0); FMA2(acc[1][1], aa1, b1);
            FMA2(acc[1][2], aa1, b2); FMA2(acc[1][3], aa1, b3);
            FMA2(acc[2][0], aa2, b0); FMA2(acc[2][1], aa2, b1);
            FMA2(acc[2][2], aa2, b2); FMA2(acc[2][3], aa2, b3);
            FMA2(acc[3][0], aa3, b0); FMA2(acc[3][1], aa3, b1);
            FMA2(acc[3][2], aa3, b2); FMA2(acc[3][3], aa3, b3);
        }
        __syncthreads();
    }

    float bv[8];
    if (bias) {
        float4 t0 = *(const float4*)(bias + bn + tn8);
        float4 t1 = *(const float4*)(bias + bn + tn8 + 4);
        bv[0] = t0.x; bv[1] = t0.y; bv[2] = t0.z; bv[3] = t0.w;
        bv[4] = t1.x; bv[5] = t1.y; bv[6] = t1.z; bv[7] = t1.w;
    } else {
#pragma unroll
        for (int q = 0; q < 8; ++q) bv[q] = 0.f;
    }
#pragma unroll
    for (int im = 0; im < 4; ++im) {
        float o[8];
#pragma unroll
        for (int p = 0; p < 4; ++p) unpk2(o[2 * p], o[2 * p + 1], acc[im][p]);
#pragma unroll
        for (int q = 0; q < 8; ++q) o[q] += bv[q];
        float4* cp = reinterpret_cast<float4*>(
            C + (size_t)(bm + tm4 + im) * ldc + bn + tn8);
        cp[0] = make_float4(o[0], o[1], o[2], o[3]);
        cp[1] = make_float4(o[4], o[5], o[6], o[7]);
    }
}

__global__ void lstm_update(const float* __restrict__ gx_t, int t) {
    int idx = blockIdx.x * blockDim.x + threadIdx.x;
    int b = idx >> 10, j = idx & 1023;
    int base = b << 12;

    float gi = g_gbase[base + j]        + gx_t[base + j];
    float gf = g_gbase[base + 1024 + j] + gx_t[base + 1024 + j];
    float gg = g_gbase[base + 2048 + j] + gx_t[base + 2048 + j];
    float go = g_gbase[base + 3072 + j] + gx_t[base + 3072 + j];

    if (t > 0) {
#pragma unroll
        for (int s = 0; s < RSPLIT; ++s) {
            const float* pp = g_part + (size_t)s * TB * G4 + base;
            gi += pp[j];
            gf += pp[1024 + j];
            gg += pp[2048 + j];
            go += pp[3072 + j];
        }
    }

    float i_ = 1.f / (1.f + expf(-gi));
    float f_ = 1.f / (1.f + expf(-gf));
    float o_ = 1.f / (1.f + expf(-go));
    float g_ = tanhf(gg);

    float c_old = (t == 0) ? 0.f : g_c[idx];
    float cn = f_ * c_old + i_ * g_;
    float hn = o_ * tanhf(cn);

    g_c[idx] = cn;
    g_h[idx] = hn;
    g_hs[(size_t)t * (TB * HID) + idx] = hn;
}

// ---------------------------------------------------------------------------
extern "C" void kernel_launch(void* const* d_in, const int* in_sizes, int n_in,
                              void* d_out, int out_size) {
    const float* features = (const float*)d_in[0];
    const int*   captions = (const int*)  d_in[1];
    const float* embed    = (const float*)d_in[3];
    const float* W_ih     = (const float*)d_in[4];
    const float* W_hh     = (const float*)d_in[5];
    const float* b_ih     = (const float*)d_in[6];
    const float* b_hh     = (const float*)d_in[7];
    const float* lin_W    = (const float*)d_in[10];
    const float* lin_b    = (const float*)d_in[11];
    float* out = (float*)d_out;

    float *p_ctx, *p_gbase, *p_gx, *p_h, *p_part, *p_bias;
    cudaGetSymbolAddress((void**)&p_ctx,   g_ctx);
    cudaGetSymbolAddress((void**)&p_gbase, g_gbase);
    cudaGetSymbolAddress((void**)&p_gx,    g_gx);
    cudaGetSymbolAddress((void**)&p_h,     g_h);
    cudaGetSymbolAddress((void**)&p_part,  g_part);
    cudaGetSymbolAddress((void**)&p_bias,  g_bias);
    void *p_WL1, *p_Hs1, *p_Wx3, *p_A3;
    cudaGetSymbolAddress(&p_WL1, g_WL1);
    cudaGetSymbolAddress(&p_Hs1, g_Hs1);
    cudaGetSymbolAddress(&p_Wx3, g_Wx3);
    cudaGetSymbolAddress(&p_A3,  g_A3);

    cudaFuncSetAttribute(mma_gemm<false>,
                         cudaFuncAttributeMaxDynamicSharedMemorySize, MM_SMEM);
    cudaFuncSetAttribute(mma_gemm<true>,
                         cudaFuncAttributeMaxDynamicSharedMemorySize, MM_SMEM);

    prep_kernel<<<16, 256>>>(captions, b_ih, b_hh);
    ctx_kernel<<<(TB * HID) / 256, 256>>>(features);

    split_lin<<<(VOC * 256) / 256, 256>>>(lin_W);
    split_wx <<<(G4 * 128) / 256, 256>>>(W_ih);
    split_emb<<<(MPAD * 128) / 256, 256>>>(embed);

    // gbase = ctx @ W_ih[:,512:]^T + (b_ih + b_hh)   (fp32)
    sgemm_kernel<<<dim3(1, 32, 1), 256>>>(p_ctx, HID,
                                          W_ih + EMB, EMB + HID,
                                          p_gbase, G4, HID, 0, p_bias);

    // gx = A3 @ Wx3^T   (bf16x3)  M=2048 N=4096 K'=1536
    mma_gemm<false><<<dim3(MPAD / 128, G4 / 128), 256, MM_SMEM>>>(
        p_A3, p_Wx3, KX, p_gx, G4, MROWS, nullptr);

    for (int t = 0; t < TT; ++t) {
        if (t > 0) {
            // part[z] = h @ W_hh^T (K slice z)  split-K 8, 256 CTAs
            sgemm_kernel<<<dim3(1, 32, RSPLIT), 256>>>(p_h, HID,
                                                       W_hh, HID,
                                                       p_part, G4, HID / RSPLIT,
                                                       TB * G4, nullptr);
        }
        lstm_update<<<(TB * HID) / 256, 256>>>(p_gx + (size_t)t * TB * G4, t);
    }

    split_hs<<<(MPAD * 256) / 256, 256>>>();

    // out = Hs1 @ WL1^T + lin_b   (fp16, K=1024)  M=2048 N=32000
    mma_gemm<true><<<dim3(MPAD / 128, VOC / 128), 256, MM_SMEM>>>(
        p_Hs1, p_WL1, HID, out, VOC, MROWS, lin_b);
}